// round 9
// baseline (speedup 1.0000x reference)
#include <cuda_runtime.h>
#include <cstdint>

#define NB 32768
#define NT 64

typedef unsigned long long u64;

__device__ int g_idx[NB];

// ---- f32x2 packed helpers (sm_100+), .b64 regs ----
__device__ __forceinline__ u64 splat2(float w) {
    u64 d; asm("mov.b64 %0, {%1, %1};" : "=l"(d) : "f"(w)); return d;
}
__device__ __forceinline__ u64 pk2(float a, float b) {
    u64 d; asm("mov.b64 %0, {%1, %2};" : "=l"(d) : "f"(a), "f"(b)); return d;
}
__device__ __forceinline__ void upk2(u64 d, float& a, float& b) {
    asm("mov.b64 {%0, %1}, %2;" : "=f"(a), "=f"(b) : "l"(d));
}
__device__ __forceinline__ void fma2(u64& acc, u64 a, u64 b) {
    asm("fma.rn.f32x2 %0, %1, %2, %3;" : "=l"(acc) : "l"(a), "l"(b), "l"(acc));
}
__device__ __forceinline__ void lds2(uint32_t addr, u64& a, u64& b) {
    asm volatile("ld.shared.v2.b64 {%0, %1}, [%2];" : "=l"(a), "=l"(b) : "r"(addr));
}
__device__ __forceinline__ void sts128(uint32_t addr, float a, float b, float c, float d) {
    asm volatile("st.shared.v4.f32 [%0], {%1, %2, %3, %4};"
                 :: "r"(addr), "f"(a), "f"(b), "f"(c), "f"(d) : "memory");
}
__device__ __forceinline__ float rcpa(float x) {
    float r; asm("rcp.approx.ftz.f32 %0, %1;" : "=f"(r) : "f"(x)); return r;
}
__device__ __forceinline__ float tanhfast(float x) {
    float e = __expf(-2.f * x);
    return __fdividef(2.f, 1.f + e) - 1.f;
}

struct SmemGRU {
    u64   Whh2[192][64];   // pre-splatted (w,w) pairs; broadcast lds -> 0 MOVs, 1 phase
    float Whd[4][64];
    float bhd[4];
    float H[4][64][4];     // [warp][k][sample]; 16B rows: one broadcast v2.b64 per k
};

// 2048 CTAs x 128 threads, 2 CTAs/SM; each warp INDEPENDENTLY owns 4 samples.
// Lane owns units u0=lane, u1=lane+32 (gate rows u, u+64, u+128). No inter-warp sync.
__global__ void __launch_bounds__(128, 2) gru_sel_kernel(
    const float* __restrict__ Hn,
    const float* __restrict__ gum,
    const float* __restrict__ Wih,
    const float* __restrict__ Whh,
    const float* __restrict__ bih,
    const float* __restrict__ bhh,
    const float* __restrict__ Whead,
    const float* __restrict__ bhead,
    float* __restrict__ out)
{
    extern __shared__ char smem_raw[];
    SmemGRU& S = *reinterpret_cast<SmemGRU*>(smem_raw);
    const int tid = threadIdx.x;

    // build duplicated weight table (one-time, ~96 iters)
    for (int i = tid; i < 192 * 64; i += 128) {
        const float v = __ldg(&Whh[i]);
        S.Whh2[i >> 6][i & 63] = splat2(v);
    }
    for (int i = tid; i < 256; i += 128) S.Whd[i >> 6][i & 63] = Whead[i];
    if (tid < 4) S.bhd[tid] = bhead[tid];
    for (int i = tid; i < 4 * 64 * 4; i += 128) (&S.H[0][0][0])[i] = 0.f;
    __syncthreads();

    const int w = tid >> 5, lane = tid & 31;
    const int u0 = lane, u1 = lane + 32;
    const int b0 = (blockIdx.x * 4 + w) * 4;        // warp's 4 samples
    const float* hp = Hn + (size_t)b0 * (NT * 4);

    const uint32_t HR = (uint32_t)__cvta_generic_to_shared(&S.H[w][0][0]);
    const uint32_t WB = (uint32_t)__cvta_generic_to_shared(&S.Whh2[0][0]);
    const uint32_t WA0 = WB + u0 * 512;          // row u0       (R gate)
    const uint32_t WB0 = WB + (u0 + 64) * 512;   // row u0+64    (Z gate)
    const uint32_t WC0 = WB + (u0 + 128) * 512;  // row u0+128   (N gate)
    const uint32_t WA1 = WB + u1 * 512;
    const uint32_t WB1 = WB + (u1 + 64) * 512;
    const uint32_t WC1 = WB + (u1 + 128) * 512;

    // biases (registers, splatted once)
    const u64 br0 = splat2(__ldg(&bih[u0])       + __ldg(&bhh[u0]));
    const u64 bz0 = splat2(__ldg(&bih[64 + u0])  + __ldg(&bhh[64 + u0]));
    const u64 bi0 = splat2(__ldg(&bih[128 + u0]));
    const u64 bh0 = splat2(__ldg(&bhh[128 + u0]));
    const u64 br1 = splat2(__ldg(&bih[u1])       + __ldg(&bhh[u1]));
    const u64 bz1 = splat2(__ldg(&bih[64 + u1])  + __ldg(&bhh[64 + u1]));
    const u64 bi1 = splat2(__ldg(&bih[128 + u1]));
    const u64 bh1 = splat2(__ldg(&bhh[128 + u1]));

    // W_ih rows (t-invariant, pre-splatted registers: 24 u64)
    u64 wiR0[4], wiZ0[4], wiN0[4], wiR1[4], wiZ1[4], wiN1[4];
    {
        const float4 a = __ldg((const float4*)(Wih + (size_t)u0 * 4));
        const float4 b = __ldg((const float4*)(Wih + (size_t)(64 + u0) * 4));
        const float4 c = __ldg((const float4*)(Wih + (size_t)(128 + u0) * 4));
        const float4 d = __ldg((const float4*)(Wih + (size_t)u1 * 4));
        const float4 e = __ldg((const float4*)(Wih + (size_t)(64 + u1) * 4));
        const float4 f = __ldg((const float4*)(Wih + (size_t)(128 + u1) * 4));
        wiR0[0]=splat2(a.x); wiR0[1]=splat2(a.y); wiR0[2]=splat2(a.z); wiR0[3]=splat2(a.w);
        wiZ0[0]=splat2(b.x); wiZ0[1]=splat2(b.y); wiZ0[2]=splat2(b.z); wiZ0[3]=splat2(b.w);
        wiN0[0]=splat2(c.x); wiN0[1]=splat2(c.y); wiN0[2]=splat2(c.z); wiN0[3]=splat2(c.w);
        wiR1[0]=splat2(d.x); wiR1[1]=splat2(d.y); wiR1[2]=splat2(d.z); wiR1[3]=splat2(d.w);
        wiZ1[0]=splat2(e.x); wiZ1[1]=splat2(e.y); wiZ1[2]=splat2(e.z); wiZ1[3]=splat2(e.w);
        wiN1[0]=splat2(f.x); wiN1[1]=splat2(f.y); wiN1[2]=splat2(f.z); wiN1[3]=splat2(f.w);
    }

    u64 ar[2][2], az[2][2], ahn[2][2], ain[2][2];
    float hreg[2][4] = {{0.f, 0.f, 0.f, 0.f}, {0.f, 0.f, 0.f, 0.f}};

#pragma unroll 1
    for (int t = 0; t < NT; t++) {
        // ---- issue gmem input loads first; recurrence below hides their latency ----
        float4 xa0 = __ldg((const float4*)(hp + ((size_t)0 * NT + t) * 4));
        float4 xb0 = __ldg((const float4*)(hp + ((size_t)1 * NT + t) * 4));
        float4 xa1 = __ldg((const float4*)(hp + ((size_t)2 * NT + t) * 4));
        float4 xb1 = __ldg((const float4*)(hp + ((size_t)3 * NT + t) * 4));

        // init accumulators with biases
        ar[0][0] = br0; ar[0][1] = br0; ar[1][0] = br1; ar[1][1] = br1;
        az[0][0] = bz0; az[0][1] = bz0; az[1][0] = bz1; az[1][1] = bz1;
        ahn[0][0] = bh0; ahn[0][1] = bh0; ahn[1][0] = bh1; ahn[1][1] = bh1;

        // ---- recurrence: 6 gate rows x 64-dot; all LDS broadcast, zero splats ----
#pragma unroll 4
        for (int kc = 0; kc < 64; kc += 4) {
            u64 hk[4][2];   // [k][sp]
#pragma unroll
            for (int k = 0; k < 4; k++)
                lds2(HR + (kc + k) * 16, hk[k][0], hk[k][1]);
#define RROW(WADDR, ACC)                                                  \
            {   u64 w0, w1, w2, w3;                                       \
                lds2((WADDR) + kc * 8,      w0, w1);                      \
                lds2((WADDR) + kc * 8 + 16, w2, w3);                      \
                _Pragma("unroll")                                         \
                for (int sp = 0; sp < 2; sp++) {                          \
                    fma2(ACC[sp], w0, hk[0][sp]);                         \
                    fma2(ACC[sp], w1, hk[1][sp]);                         \
                    fma2(ACC[sp], w2, hk[2][sp]);                         \
                    fma2(ACC[sp], w3, hk[3][sp]);                         \
                } }
            RROW(WA0, ar[0])
            RROW(WB0, az[0])
            RROW(WC0, ahn[0])
            RROW(WA1, ar[1])
            RROW(WB1, az[1])
            RROW(WC1, ahn[1])
        }
        __syncwarp();   // all lanes done reading old H

        // ---- input contributions (loads have landed by now) ----
        {
            u64 xp[4][2];
            xp[0][0] = pk2(xa0.x, xb0.x); xp[0][1] = pk2(xa1.x, xb1.x);
            xp[1][0] = pk2(xa0.y, xb0.y); xp[1][1] = pk2(xa1.y, xb1.y);
            xp[2][0] = pk2(xa0.z, xb0.z); xp[2][1] = pk2(xa1.z, xb1.z);
            xp[3][0] = pk2(xa0.w, xb0.w); xp[3][1] = pk2(xa1.w, xb1.w);
#pragma unroll
            for (int sp = 0; sp < 2; sp++) {
                fma2(ar[0][sp], wiR0[0], xp[0][sp]); fma2(ar[0][sp], wiR0[1], xp[1][sp]);
                fma2(ar[0][sp], wiR0[2], xp[2][sp]); fma2(ar[0][sp], wiR0[3], xp[3][sp]);
                fma2(az[0][sp], wiZ0[0], xp[0][sp]); fma2(az[0][sp], wiZ0[1], xp[1][sp]);
                fma2(az[0][sp], wiZ0[2], xp[2][sp]); fma2(az[0][sp], wiZ0[3], xp[3][sp]);
                u64 aN = bi0;
                fma2(aN, wiN0[0], xp[0][sp]); fma2(aN, wiN0[1], xp[1][sp]);
                fma2(aN, wiN0[2], xp[2][sp]); fma2(aN, wiN0[3], xp[3][sp]);
                ain[0][sp] = aN;
                fma2(ar[1][sp], wiR1[0], xp[0][sp]); fma2(ar[1][sp], wiR1[1], xp[1][sp]);
                fma2(ar[1][sp], wiR1[2], xp[2][sp]); fma2(ar[1][sp], wiR1[3], xp[3][sp]);
                fma2(az[1][sp], wiZ1[0], xp[0][sp]); fma2(az[1][sp], wiZ1[1], xp[1][sp]);
                fma2(az[1][sp], wiZ1[2], xp[2][sp]); fma2(az[1][sp], wiZ1[3], xp[3][sp]);
                u64 bN = bi1;
                fma2(bN, wiN1[0], xp[0][sp]); fma2(bN, wiN1[1], xp[1][sp]);
                fma2(bN, wiN1[2], xp[2][sp]); fma2(bN, wiN1[3], xp[3][sp]);
                ain[1][sp] = bN;
            }
        }

        // ---- activations: paired-rcp sigmoids; own h kept in registers ----
#pragma unroll
        for (int un = 0; un < 2; un++) {
#pragma unroll
            for (int sp = 0; sp < 2; sp++) {
                float dra, drb, dza, dzb, dia, dib, dna, dnb;
                upk2(ar[un][sp],  dra, drb);
                upk2(az[un][sp],  dza, dzb);
                upk2(ain[un][sp], dia, dib);
                upk2(ahn[un][sp], dna, dnb);
#pragma unroll
                for (int h = 0; h < 2; h++) {
                    const float dr = h ? drb : dra;
                    const float dz = h ? dzb : dza;
                    const float di = h ? dib : dia;
                    const float dn = h ? dnb : dna;
                    const int s = 2 * sp + h;
                    const float er = __expf(-dr), ez = __expf(-dz);
                    const float A = 1.f + er, B = 1.f + ez;
                    const float ip = rcpa(A * B);     // shared rcp for both sigmoids
                    const float r  = B * ip;          // sigmoid(dr)
                    const float zv = A * ip;          // sigmoid(dz)
                    const float et = __expf(-2.f * (di + r * dn));
                    const float n  = fmaf(2.f, rcpa(1.f + et), -1.f);   // tanh
                    hreg[un][s] = n + zv * (hreg[un][s] - n);
                }
            }
        }
        sts128(HR + u0 * 16, hreg[0][0], hreg[0][1], hreg[0][2], hreg[0][3]);
        sts128(HR + u1 * 16, hreg[1][0], hreg[1][1], hreg[1][2], hreg[1][3]);
        __syncwarp();   // new h visible to all lanes
    }

    // ---- head + gumbel argmax: lanes 0..15 -> (sample = lane>>2, mode = lane&3) ----
    if (lane < 16) {
        const int sl = lane >> 2, ml = lane & 3;
        float acc = S.bhd[ml];
#pragma unroll
        for (int k = 0; k < 64; k++)
            acc += S.Whd[ml][k] * S.H[w][k][sl];
        const int b = b0 + sl;
        const float lv = acc + __ldg(&gum[b * 4 + ml]);
        float best = lv;
        int   bi   = ml;
#pragma unroll
        for (int d = 1; d < 4; d <<= 1) {
            const float ob = __shfl_xor_sync(0x0000ffffu, best, d);
            const int   oi = __shfl_xor_sync(0x0000ffffu, bi, d);
            if (ob > best || (ob == best && oi < bi)) { best = ob; bi = oi; }
        }
        out[131072 + b * 4 + ml] = acc;                       // logits
        out[262144 + b * 4 + ml] = (ml == bi) ? 1.f : 0.f;    // onehot
        if (ml == 0) { out[393216 + b] = (float)bi; g_idx[b] = bi; }
    }
}

// Expert bank: unchanged (35us, not the bottleneck).
__global__ void __launch_bounds__(256) bank_kernel(
    const float* __restrict__ Xp,
    const float* __restrict__ dtp,
    const float* __restrict__ W1,
    const float* __restrict__ b1,
    const float* __restrict__ W2,
    const float* __restrict__ b2,
    float* __restrict__ out)
{
    __shared__ float sW1[4 * 5 * 256];
    __shared__ float sb1[4 * 256];
    __shared__ float sW2[4][256][5];
    __shared__ float sb2[16];
    const int tid = threadIdx.x;
    for (int i = tid; i < 5120; i += 256) sW1[i] = W1[i];
    for (int i = tid; i < 1024; i += 256) sb1[i] = b1[i];
    for (int i = tid; i < 4096; i += 256) sW2[i >> 10][(i >> 2) & 255][i & 3] = W2[i];
    if (tid < 16) sb2[tid] = b2[tid];
    __syncthreads();

    const float dt = __ldg(dtp);
    const int gw = blockIdx.x * 8 + (tid >> 5);
    const int lane = tid & 31;
#pragma unroll 1
    for (int it = 0; it < 8; it++) {
        const int b = gw * 8 + it;
        const int e = g_idx[b];
        const float4 xv = __ldg((const float4*)(Xp + b * 4));
        const float* w1e = sW1 + e * 1280;
        float hid[8];
#pragma unroll
        for (int j = 0; j < 8; j++) {
            const int u = lane + 32 * j;
            float a = sb1[e * 256 + u]
                    + xv.x * w1e[0 * 256 + u]
                    + xv.y * w1e[1 * 256 + u]
                    + xv.z * w1e[2 * 256 + u]
                    + xv.w * w1e[3 * 256 + u]
                    + dt   * w1e[4 * 256 + u];
            hid[j] = tanhfast(a);
        }
        float f0 = 0.f, f1 = 0.f, f2 = 0.f, f3 = 0.f;
#pragma unroll
        for (int j = 0; j < 8; j++) {
            const int u = lane + 32 * j;
            f0 += hid[j] * sW2[e][u][0];
            f1 += hid[j] * sW2[e][u][1];
            f2 += hid[j] * sW2[e][u][2];
            f3 += hid[j] * sW2[e][u][3];
        }
#pragma unroll
        for (int off = 16; off >= 1; off >>= 1) {
            f0 += __shfl_xor_sync(0xffffffffu, f0, off);
            f1 += __shfl_xor_sync(0xffffffffu, f1, off);
            f2 += __shfl_xor_sync(0xffffffffu, f2, off);
            f3 += __shfl_xor_sync(0xffffffffu, f3, off);
        }
        if (lane < 4) {
            float fv = (lane == 0) ? f0 : (lane == 1) ? f1 : (lane == 2) ? f2 : f3;
            fv += sb2[e * 4 + lane];
            out[b * 4 + lane] = __ldg(&Xp[b * 4 + lane]) + dt * fv;
        }
    }
}

extern "C" void kernel_launch(void* const* d_in, const int* in_sizes, int n_in,
                              void* d_out, int out_size) {
    const float* Hn    = (const float*)d_in[0];
    const float* Xp    = (const float*)d_in[1];
    const float* dtp   = (const float*)d_in[2];
    const float* gum   = (const float*)d_in[3];
    const float* Wih   = (const float*)d_in[4];
    const float* Whh   = (const float*)d_in[5];
    const float* bih   = (const float*)d_in[6];
    const float* bhh   = (const float*)d_in[7];
    const float* Whead = (const float*)d_in[8];
    const float* bhead = (const float*)d_in[9];
    const float* W1    = (const float*)d_in[10];
    const float* b1    = (const float*)d_in[11];
    const float* W2    = (const float*)d_in[12];
    const float* b2    = (const float*)d_in[13];
    float* out = (float*)d_out;

    const int smem = (int)sizeof(SmemGRU);   // ~103.4 KB -> 2 CTAs/SM
    cudaFuncSetAttribute(gru_sel_kernel, cudaFuncAttributeMaxDynamicSharedMemorySize, smem);

    gru_sel_kernel<<<2048, 128, smem>>>(Hn, gum, Wih, Whh, bih, bhh, Whead, bhead, out);
    bank_kernel<<<512, 256>>>(Xp, dtp, W1, b1, W2, b2, out);
}

// round 12
// speedup vs baseline: 6.4579x; 6.4579x over previous
#include <cuda_runtime.h>
#include <cstdint>

#define NB 32768
#define NT 64
#define WROW 66   // u64 per weight row: 528B = 132 words -> (4*l)%32 bank pattern, conflict-free

typedef unsigned long long u64;

__device__ int g_idx[NB];

// ---- f32x2 packed helpers (sm_100+), .b64 regs ----
__device__ __forceinline__ u64 splat2(float w) {
    u64 d; asm("mov.b64 %0, {%1, %1};" : "=l"(d) : "f"(w)); return d;
}
__device__ __forceinline__ u64 pk2(float a, float b) {
    u64 d; asm("mov.b64 %0, {%1, %2};" : "=l"(d) : "f"(a), "f"(b)); return d;
}
__device__ __forceinline__ void upk2(u64 d, float& a, float& b) {
    asm("mov.b64 {%0, %1}, %2;" : "=f"(a), "=f"(b) : "l"(d));
}
__device__ __forceinline__ void fma2(u64& acc, u64 a, u64 b) {
    asm("fma.rn.f32x2 %0, %1, %2, %3;" : "=l"(acc) : "l"(a), "l"(b), "l"(acc));
}
__device__ __forceinline__ void lds2(uint32_t addr, u64& a, u64& b) {
    asm volatile("ld.shared.v2.b64 {%0, %1}, [%2];" : "=l"(a), "=l"(b) : "r"(addr));
}
__device__ __forceinline__ void sts128(uint32_t addr, float a, float b, float c, float d) {
    asm volatile("st.shared.v4.f32 [%0], {%1, %2, %3, %4};"
                 :: "r"(addr), "f"(a), "f"(b), "f"(c), "f"(d) : "memory");
}
__device__ __forceinline__ float rcpa(float x) {
    float r; asm("rcp.approx.ftz.f32 %0, %1;" : "=f"(r) : "f"(x)); return r;
}
__device__ __forceinline__ float tanhfast(float x) {
    float e = __expf(-2.f * x);
    return __fdividef(2.f, 1.f + e) - 1.f;
}

struct SmemGRU {
    alignas(16) u64 Whh2[192][WROW];  // pre-splatted (w,w); 528B stride -> conflict-free
    float Whd[4][64];
    float bhd[4];
    float H[4][64][4];                // [warp][k][sample]; 16B rows: one broadcast v2.b64 per k
};

// 2048 CTAs x 128 threads, 2 CTAs/SM; each warp INDEPENDENTLY owns 4 samples.
// Lane owns units u0=lane, u1=lane+32 (gate rows u, u+64, u+128). No inter-warp sync.
__global__ void __launch_bounds__(128, 2) gru_sel_kernel(
    const float* __restrict__ Hn,
    const float* __restrict__ gum,
    const float* __restrict__ Wih,
    const float* __restrict__ Whh,
    const float* __restrict__ bih,
    const float* __restrict__ bhh,
    const float* __restrict__ Whead,
    const float* __restrict__ bhead,
    float* __restrict__ out)
{
    extern __shared__ char smem_raw[];
    SmemGRU& S = *reinterpret_cast<SmemGRU*>(smem_raw);
    const int tid = threadIdx.x;

    // build duplicated weight table (one-time, ~96 iters)
    for (int i = tid; i < 192 * 64; i += 128) {
        const float v = __ldg(&Whh[i]);
        S.Whh2[i >> 6][i & 63] = splat2(v);
    }
    for (int i = tid; i < 256; i += 128) S.Whd[i >> 6][i & 63] = Whead[i];
    if (tid < 4) S.bhd[tid] = bhead[tid];
    for (int i = tid; i < 4 * 64 * 4; i += 128) (&S.H[0][0][0])[i] = 0.f;
    __syncthreads();

    const int w = tid >> 5, lane = tid & 31;
    const int u0 = lane, u1 = lane + 32;
    const int b0 = (blockIdx.x * 4 + w) * 4;        // warp's 4 samples
    const float* hp = Hn + (size_t)b0 * (NT * 4);

    const uint32_t HR = (uint32_t)__cvta_generic_to_shared(&S.H[w][0][0]);
    const uint32_t WB = (uint32_t)__cvta_generic_to_shared(&S.Whh2[0][0]);
    const uint32_t WA0 = WB + u0 * (WROW * 8);          // row u0       (R gate)
    const uint32_t WB0 = WB + (u0 + 64) * (WROW * 8);   // row u0+64    (Z gate)
    const uint32_t WC0 = WB + (u0 + 128) * (WROW * 8);  // row u0+128   (N gate)
    const uint32_t WA1 = WB + u1 * (WROW * 8);
    const uint32_t WB1 = WB + (u1 + 64) * (WROW * 8);
    const uint32_t WC1 = WB + (u1 + 128) * (WROW * 8);

    // biases (registers, splatted once)
    const u64 br0 = splat2(__ldg(&bih[u0])       + __ldg(&bhh[u0]));
    const u64 bz0 = splat2(__ldg(&bih[64 + u0])  + __ldg(&bhh[64 + u0]));
    const u64 bi0 = splat2(__ldg(&bih[128 + u0]));
    const u64 bh0 = splat2(__ldg(&bhh[128 + u0]));
    const u64 br1 = splat2(__ldg(&bih[u1])       + __ldg(&bhh[u1]));
    const u64 bz1 = splat2(__ldg(&bih[64 + u1])  + __ldg(&bhh[64 + u1]));
    const u64 bi1 = splat2(__ldg(&bih[128 + u1]));
    const u64 bh1 = splat2(__ldg(&bhh[128 + u1]));

    // W_ih rows (t-invariant, pre-splatted registers: 24 u64)
    u64 wiR0[4], wiZ0[4], wiN0[4], wiR1[4], wiZ1[4], wiN1[4];
    {
        const float4 a = __ldg((const float4*)(Wih + (size_t)u0 * 4));
        const float4 b = __ldg((const float4*)(Wih + (size_t)(64 + u0) * 4));
        const float4 c = __ldg((const float4*)(Wih + (size_t)(128 + u0) * 4));
        const float4 d = __ldg((const float4*)(Wih + (size_t)u1 * 4));
        const float4 e = __ldg((const float4*)(Wih + (size_t)(64 + u1) * 4));
        const float4 f = __ldg((const float4*)(Wih + (size_t)(128 + u1) * 4));
        wiR0[0]=splat2(a.x); wiR0[1]=splat2(a.y); wiR0[2]=splat2(a.z); wiR0[3]=splat2(a.w);
        wiZ0[0]=splat2(b.x); wiZ0[1]=splat2(b.y); wiZ0[2]=splat2(b.z); wiZ0[3]=splat2(b.w);
        wiN0[0]=splat2(c.x); wiN0[1]=splat2(c.y); wiN0[2]=splat2(c.z); wiN0[3]=splat2(c.w);
        wiR1[0]=splat2(d.x); wiR1[1]=splat2(d.y); wiR1[2]=splat2(d.z); wiR1[3]=splat2(d.w);
        wiZ1[0]=splat2(e.x); wiZ1[1]=splat2(e.y); wiZ1[2]=splat2(e.z); wiZ1[3]=splat2(e.w);
        wiN1[0]=splat2(f.x); wiN1[1]=splat2(f.y); wiN1[2]=splat2(f.z); wiN1[3]=splat2(f.w);
    }

    u64 ar[2][2], az[2][2], ahn[2][2], ain[2][2];
    float hreg[2][4] = {{0.f, 0.f, 0.f, 0.f}, {0.f, 0.f, 0.f, 0.f}};

#pragma unroll 1
    for (int t = 0; t < NT; t++) {
        // ---- issue gmem input loads first; recurrence below hides their latency ----
        float4 xa0 = __ldg((const float4*)(hp + ((size_t)0 * NT + t) * 4));
        float4 xb0 = __ldg((const float4*)(hp + ((size_t)1 * NT + t) * 4));
        float4 xa1 = __ldg((const float4*)(hp + ((size_t)2 * NT + t) * 4));
        float4 xb1 = __ldg((const float4*)(hp + ((size_t)3 * NT + t) * 4));

        // init accumulators with biases
        ar[0][0] = br0; ar[0][1] = br0; ar[1][0] = br1; ar[1][1] = br1;
        az[0][0] = bz0; az[0][1] = bz0; az[1][0] = bz1; az[1][1] = bz1;
        ahn[0][0] = bh0; ahn[0][1] = bh0; ahn[1][0] = bh1; ahn[1][1] = bh1;

        // ---- recurrence: 6 gate rows x 64-dot; broadcast H, conflict-free weights, zero splats ----
#pragma unroll 4
        for (int kc = 0; kc < 64; kc += 4) {
            u64 hk[4][2];   // [k][sp]
#pragma unroll
            for (int k = 0; k < 4; k++)
                lds2(HR + (kc + k) * 16, hk[k][0], hk[k][1]);
#define RROW(WADDR, ACC)                                                  \
            {   u64 w0, w1, w2, w3;                                       \
                lds2((WADDR) + kc * 8,      w0, w1);                      \
                lds2((WADDR) + kc * 8 + 16, w2, w3);                      \
                _Pragma("unroll")                                         \
                for (int sp = 0; sp < 2; sp++) {                          \
                    fma2(ACC[sp], w0, hk[0][sp]);                         \
                    fma2(ACC[sp], w1, hk[1][sp]);                         \
                    fma2(ACC[sp], w2, hk[2][sp]);                         \
                    fma2(ACC[sp], w3, hk[3][sp]);                         \
                } }
            RROW(WA0, ar[0])
            RROW(WB0, az[0])
            RROW(WC0, ahn[0])
            RROW(WA1, ar[1])
            RROW(WB1, az[1])
            RROW(WC1, ahn[1])
        }
        __syncwarp();   // all lanes done reading old H

        // ---- input contributions (loads have landed by now) ----
        {
            u64 xp[4][2];
            xp[0][0] = pk2(xa0.x, xb0.x); xp[0][1] = pk2(xa1.x, xb1.x);
            xp[1][0] = pk2(xa0.y, xb0.y); xp[1][1] = pk2(xa1.y, xb1.y);
            xp[2][0] = pk2(xa0.z, xb0.z); xp[2][1] = pk2(xa1.z, xb1.z);
            xp[3][0] = pk2(xa0.w, xb0.w); xp[3][1] = pk2(xa1.w, xb1.w);
#pragma unroll
            for (int sp = 0; sp < 2; sp++) {
                fma2(ar[0][sp], wiR0[0], xp[0][sp]); fma2(ar[0][sp], wiR0[1], xp[1][sp]);
                fma2(ar[0][sp], wiR0[2], xp[2][sp]); fma2(ar[0][sp], wiR0[3], xp[3][sp]);
                fma2(az[0][sp], wiZ0[0], xp[0][sp]); fma2(az[0][sp], wiZ0[1], xp[1][sp]);
                fma2(az[0][sp], wiZ0[2], xp[2][sp]); fma2(az[0][sp], wiZ0[3], xp[3][sp]);
                u64 aN = bi0;
                fma2(aN, wiN0[0], xp[0][sp]); fma2(aN, wiN0[1], xp[1][sp]);
                fma2(aN, wiN0[2], xp[2][sp]); fma2(aN, wiN0[3], xp[3][sp]);
                ain[0][sp] = aN;
                fma2(ar[1][sp], wiR1[0], xp[0][sp]); fma2(ar[1][sp], wiR1[1], xp[1][sp]);
                fma2(ar[1][sp], wiR1[2], xp[2][sp]); fma2(ar[1][sp], wiR1[3], xp[3][sp]);
                fma2(az[1][sp], wiZ1[0], xp[0][sp]); fma2(az[1][sp], wiZ1[1], xp[1][sp]);
                fma2(az[1][sp], wiZ1[2], xp[2][sp]); fma2(az[1][sp], wiZ1[3], xp[3][sp]);
                u64 bN = bi1;
                fma2(bN, wiN1[0], xp[0][sp]); fma2(bN, wiN1[1], xp[1][sp]);
                fma2(bN, wiN1[2], xp[2][sp]); fma2(bN, wiN1[3], xp[3][sp]);
                ain[1][sp] = bN;
            }
        }

        // ---- activations: paired-rcp sigmoids; own h kept in registers ----
#pragma unroll
        for (int un = 0; un < 2; un++) {
#pragma unroll
            for (int sp = 0; sp < 2; sp++) {
                float dra, drb, dza, dzb, dia, dib, dna, dnb;
                upk2(ar[un][sp],  dra, drb);
                upk2(az[un][sp],  dza, dzb);
                upk2(ain[un][sp], dia, dib);
                upk2(ahn[un][sp], dna, dnb);
#pragma unroll
                for (int h = 0; h < 2; h++) {
                    const float dr = h ? drb : dra;
                    const float dz = h ? dzb : dza;
                    const float di = h ? dib : dia;
                    const float dn = h ? dnb : dna;
                    const int s = 2 * sp + h;
                    const float er = __expf(-dr), ez = __expf(-dz);
                    const float A = 1.f + er, B = 1.f + ez;
                    const float ip = rcpa(A * B);     // shared rcp for both sigmoids
                    const float r  = B * ip;          // sigmoid(dr)
                    const float zv = A * ip;          // sigmoid(dz)
                    const float et = __expf(-2.f * (di + r * dn));
                    const float n  = fmaf(2.f, rcpa(1.f + et), -1.f);   // tanh
                    hreg[un][s] = n + zv * (hreg[un][s] - n);
                }
            }
        }
        sts128(HR + u0 * 16, hreg[0][0], hreg[0][1], hreg[0][2], hreg[0][3]);
        sts128(HR + u1 * 16, hreg[1][0], hreg[1][1], hreg[1][2], hreg[1][3]);
        __syncwarp();   // new h visible to all lanes
    }

    // ---- head + gumbel argmax: lanes 0..15 -> (sample = lane>>2, mode = lane&3) ----
    if (lane < 16) {
        const int sl = lane >> 2, ml = lane & 3;
        float acc = S.bhd[ml];
#pragma unroll
        for (int k = 0; k < 64; k++)
            acc += S.Whd[ml][k] * S.H[w][k][sl];
        const int b = b0 + sl;
        const float lv = acc + __ldg(&gum[b * 4 + ml]);
        float best = lv;
        int   bi   = ml;
#pragma unroll
        for (int d = 1; d < 4; d <<= 1) {
            const float ob = __shfl_xor_sync(0x0000ffffu, best, d);
            const int   oi = __shfl_xor_sync(0x0000ffffu, bi, d);
            if (ob > best || (ob == best && oi < bi)) { best = ob; bi = oi; }
        }
        out[131072 + b * 4 + ml] = acc;                       // logits
        out[262144 + b * 4 + ml] = (ml == bi) ? 1.f : 0.f;    // onehot
        if (ml == 0) { out[393216 + b] = (float)bi; g_idx[b] = bi; }
    }
}

// Expert bank: unchanged (35us, not the bottleneck).
__global__ void __launch_bounds__(256) bank_kernel(
    const float* __restrict__ Xp,
    const float* __restrict__ dtp,
    const float* __restrict__ W1,
    const float* __restrict__ b1,
    const float* __restrict__ W2,
    const float* __restrict__ b2,
    float* __restrict__ out)
{
    __shared__ float sW1[4 * 5 * 256];
    __shared__ float sb1[4 * 256];
    __shared__ float sW2[4][256][5];
    __shared__ float sb2[16];
    const int tid = threadIdx.x;
    for (int i = tid; i < 5120; i += 256) sW1[i] = W1[i];
    for (int i = tid; i < 1024; i += 256) sb1[i] = b1[i];
    for (int i = tid; i < 4096; i += 256) sW2[i >> 10][(i >> 2) & 255][i & 3] = W2[i];
    if (tid < 16) sb2[tid] = b2[tid];
    __syncthreads();

    const float dt = __ldg(dtp);
    const int gw = blockIdx.x * 8 + (tid >> 5);
    const int lane = tid & 31;
#pragma unroll 1
    for (int it = 0; it < 8; it++) {
        const int b = gw * 8 + it;
        const int e = g_idx[b];
        const float4 xv = __ldg((const float4*)(Xp + b * 4));
        const float* w1e = sW1 + e * 1280;
        float hid[8];
#pragma unroll
        for (int j = 0; j < 8; j++) {
            const int u = lane + 32 * j;
            float a = sb1[e * 256 + u]
                    + xv.x * w1e[0 * 256 + u]
                    + xv.y * w1e[1 * 256 + u]
                    + xv.z * w1e[2 * 256 + u]
                    + xv.w * w1e[3 * 256 + u]
                    + dt   * w1e[4 * 256 + u];
            hid[j] = tanhfast(a);
        }
        float f0 = 0.f, f1 = 0.f, f2 = 0.f, f3 = 0.f;
#pragma unroll
        for (int j = 0; j < 8; j++) {
            const int u = lane + 32 * j;
            f0 += hid[j] * sW2[e][u][0];
            f1 += hid[j] * sW2[e][u][1];
            f2 += hid[j] * sW2[e][u][2];
            f3 += hid[j] * sW2[e][u][3];
        }
#pragma unroll
        for (int off = 16; off >= 1; off >>= 1) {
            f0 += __shfl_xor_sync(0xffffffffu, f0, off);
            f1 += __shfl_xor_sync(0xffffffffu, f1, off);
            f2 += __shfl_xor_sync(0xffffffffu, f2, off);
            f3 += __shfl_xor_sync(0xffffffffu, f3, off);
        }
        if (lane < 4) {
            float fv = (lane == 0) ? f0 : (lane == 1) ? f1 : (lane == 2) ? f2 : f3;
            fv += sb2[e * 4 + lane];
            out[b * 4 + lane] = __ldg(&Xp[b * 4 + lane]) + dt * fv;
        }
    }
}

extern "C" void kernel_launch(void* const* d_in, const int* in_sizes, int n_in,
                              void* d_out, int out_size) {
    const float* Hn    = (const float*)d_in[0];
    const float* Xp    = (const float*)d_in[1];
    const float* dtp   = (const float*)d_in[2];
    const float* gum   = (const float*)d_in[3];
    const float* Wih   = (const float*)d_in[4];
    const float* Whh   = (const float*)d_in[5];
    const float* bih   = (const float*)d_in[6];
    const float* bhh   = (const float*)d_in[7];
    const float* Whead = (const float*)d_in[8];
    const float* bhead = (const float*)d_in[9];
    const float* W1    = (const float*)d_in[10];
    const float* b1    = (const float*)d_in[11];
    const float* W2    = (const float*)d_in[12];
    const float* b2    = (const float*)d_in[13];
    float* out = (float*)d_out;

    const int smem = (int)sizeof(SmemGRU);   // ~104.6 KB -> 2 CTAs/SM
    cudaFuncSetAttribute(gru_sel_kernel, cudaFuncAttributeMaxDynamicSharedMemorySize, smem);

    gru_sel_kernel<<<2048, 128, smem>>>(Hn, gum, Wih, Whh, bih, bhh, Whead, bhead, out);
    bank_kernel<<<512, 256>>>(Xp, dtp, W1, b1, W2, b2, out);
}

// round 13
// speedup vs baseline: 7.1020x; 1.0997x over previous
#include <cuda_runtime.h>
#include <cstdint>

#define NB 32768
#define NT 64

typedef unsigned long long u64;

__device__ int g_idx[NB];

// ---- f32x2 packed helpers (sm_100+), .b64 regs ----
__device__ __forceinline__ u64 splat2(float w) {
    u64 d; asm("mov.b64 %0, {%1, %1};" : "=l"(d) : "f"(w)); return d;
}
__device__ __forceinline__ u64 pk2(float a, float b) {
    u64 d; asm("mov.b64 %0, {%1, %2};" : "=l"(d) : "f"(a), "f"(b)); return d;
}
__device__ __forceinline__ void upk2(u64 d, float& a, float& b) {
    asm("mov.b64 {%0, %1}, %2;" : "=f"(a), "=f"(b) : "l"(d));
}
__device__ __forceinline__ void fma2(u64& acc, u64 a, u64 b) {
    asm("fma.rn.f32x2 %0, %1, %2, %3;" : "=l"(acc) : "l"(a), "l"(b), "l"(acc));
}
__device__ __forceinline__ void lds2(uint32_t addr, u64& a, u64& b) {
    asm volatile("ld.shared.v2.b64 {%0, %1}, [%2];" : "=l"(a), "=l"(b) : "r"(addr));
}
__device__ __forceinline__ u64 lds64(uint32_t addr) {
    u64 d; asm volatile("ld.shared.b64 %0, [%1];" : "=l"(d) : "r"(addr)); return d;
}
__device__ __forceinline__ float lds32f(uint32_t addr) {
    float f; asm volatile("ld.shared.f32 %0, [%1];" : "=f"(f) : "r"(addr)); return f;
}
__device__ __forceinline__ void sts64(uint32_t addr, u64 v) {
    asm volatile("st.shared.b64 [%0], %1;" :: "r"(addr), "l"(v) : "memory");
}
__device__ __forceinline__ float rcpa(float x) {
    float r; asm("rcp.approx.ftz.f32 %0, %1;" : "=f"(r) : "f"(x)); return r;
}
__device__ __forceinline__ float tanhfast(float x) {
    float e = __expf(-2.f * x);
    return __fdividef(2.f, 1.f + e) - 1.f;
}

// Unit-packed layout: every u64 = (value for unit l, value for unit l+32).
struct SmemGRU {
    u64 WT[3][32][32][2];   // [gate][kpair][lane][j]: Whh unit-pairs; lane stride 16B -> conflict-free LDS.128
    u64 WI[3][4][32];       // W_ih unit-pairs
    u64 BI[4][32];          // biases: r(ih+hh), z(ih+hh), in(ih), hn(hh) unit-pairs
    u64 H2[8][8][64];       // [warp][sample][k] = (h,h) splat pairs; recurrence reads are broadcasts
};  // 84 KB

// 512 CTAs x 256 threads, 2 CTAs/SM (16 warps/SM); each warp INDEPENDENTLY owns 8 samples.
// Lane owns unit-pair (lane, lane+32) packed into f32x2 lanes. No inter-warp sync.
__global__ void __launch_bounds__(256, 2) gru_sel_kernel(
    const float* __restrict__ Hn,
    const float* __restrict__ gum,
    const float* __restrict__ Wih,
    const float* __restrict__ Whh,
    const float* __restrict__ bih,
    const float* __restrict__ bhh,
    const float* __restrict__ Whead,
    const float* __restrict__ bhead,
    float* __restrict__ out)
{
    extern __shared__ char smem_raw[];
    SmemGRU& S = *reinterpret_cast<SmemGRU*>(smem_raw);
    const int tid = threadIdx.x;

    // one-time: build unit-paired weight tables
    for (int i = tid; i < 3 * 64 * 32; i += 256) {   // i = (g*64 + k)*32 + l
        const int l = i & 31, k = (i >> 5) & 63, g = i >> 11;
        const float a = __ldg(&Whh[(g * 64 + l) * 64 + k]);
        const float b = __ldg(&Whh[(g * 64 + l + 32) * 64 + k]);
        S.WT[g][k >> 1][l][k & 1] = pk2(a, b);
    }
    for (int i = tid; i < 3 * 4 * 32; i += 256) {    // i = (g*4 + j)*32 + l
        const int l = i & 31, j = (i >> 5) & 3, g = i >> 7;
        S.WI[g][j][l] = pk2(__ldg(&Wih[(g * 64 + l) * 4 + j]),
                            __ldg(&Wih[(g * 64 + l + 32) * 4 + j]));
    }
    if (tid < 32) {
        const int l = tid;
        S.BI[0][l] = pk2(__ldg(&bih[l])       + __ldg(&bhh[l]),
                         __ldg(&bih[l + 32])  + __ldg(&bhh[l + 32]));
        S.BI[1][l] = pk2(__ldg(&bih[64 + l])  + __ldg(&bhh[64 + l]),
                         __ldg(&bih[96 + l])  + __ldg(&bhh[96 + l]));
        S.BI[2][l] = pk2(__ldg(&bih[128 + l]), __ldg(&bih[160 + l]));
        S.BI[3][l] = pk2(__ldg(&bhh[128 + l]), __ldg(&bhh[160 + l]));
    }
    __syncthreads();

    const int w = tid >> 5, lane = tid & 31;
    const int b0 = (blockIdx.x * 8 + w) * 8;        // warp's 8 samples
    const float* hp = Hn + (size_t)b0 * (NT * 4);

    const uint32_t H2b = (uint32_t)__cvta_generic_to_shared(&S.H2[w][0][0]);
    const uint32_t WTl = (uint32_t)__cvta_generic_to_shared(&S.WT[0][0][0][0]) + lane * 16;
    const uint32_t WIl = (uint32_t)__cvta_generic_to_shared(&S.WI[0][0][0]) + lane * 8;
    const uint32_t BIl = (uint32_t)__cvta_generic_to_shared(&S.BI[0][0]) + lane * 8;

    // biases in regs (8 regs)
    const u64 bR  = lds64(BIl + 0 * 256);
    const u64 bZ  = lds64(BIl + 1 * 256);
    const u64 bIN = lds64(BIl + 2 * 256);
    const u64 bHN = lds64(BIl + 3 * 256);

    u64 ar[8], az[8], ahn[8], ain[8];
    float hreg[2][8];
#pragma unroll
    for (int s = 0; s < 8; s++) { hreg[0][s] = 0.f; hreg[1][s] = 0.f; }

#pragma unroll 1
    for (int t = 0; t < NT; t++) {
        // ---- input phase: W_ih unit-pairs from smem, x splatted ----
        u64 wi[3][4];
#pragma unroll
        for (int g = 0; g < 3; g++)
#pragma unroll
            for (int j = 0; j < 4; j++)
                wi[g][j] = lds64(WIl + (g * 4 + j) * 256);
#pragma unroll
        for (int s = 0; s < 8; s++) {
            const float4 x = __ldg((const float4*)(hp + ((size_t)s * NT + t) * 4));
            const u64 x0 = splat2(x.x), x1 = splat2(x.y), x2 = splat2(x.z), x3 = splat2(x.w);
            u64 aR = bR;
            fma2(aR, wi[0][0], x0); fma2(aR, wi[0][1], x1);
            fma2(aR, wi[0][2], x2); fma2(aR, wi[0][3], x3);
            u64 aZ = bZ;
            fma2(aZ, wi[1][0], x0); fma2(aZ, wi[1][1], x1);
            fma2(aZ, wi[1][2], x2); fma2(aZ, wi[1][3], x3);
            u64 aN = bIN;
            fma2(aN, wi[2][0], x0); fma2(aN, wi[2][1], x1);
            fma2(aN, wi[2][2], x2); fma2(aN, wi[2][3], x3);
            ar[s] = aR; az[s] = aZ; ain[s] = aN; ahn[s] = bHN;
        }

        // ---- recurrence: weights load pre-paired (zero splats), h loads broadcast ----
        if (t) {
#pragma unroll 2
            for (int kp = 0; kp < 32; kp++) {
                u64 wr0, wr1, wz0, wz1, wn0, wn1;
                lds2(WTl + (0 * 32 + kp) * 512, wr0, wr1);
                lds2(WTl + (1 * 32 + kp) * 512, wz0, wz1);
                lds2(WTl + (2 * 32 + kp) * 512, wn0, wn1);
#pragma unroll
                for (int s = 0; s < 8; s++) {
                    u64 h0, h1;
                    lds2(H2b + s * 512 + kp * 16, h0, h1);   // (h,h) for k=2kp, 2kp+1
                    fma2(ar[s],  wr0, h0); fma2(ar[s],  wr1, h1);
                    fma2(az[s],  wz0, h0); fma2(az[s],  wz1, h1);
                    fma2(ahn[s], wn0, h0); fma2(ahn[s], wn1, h1);
                }
            }
        }
        __syncwarp();   // all lanes done reading old H2

        // ---- activations: paired-rcp sigmoids; write (h,h) splats back to H2 ----
#pragma unroll
        for (int s = 0; s < 8; s++) {
            float dr0, dr1, dz0, dz1, di0, di1, dn0, dn1;
            upk2(ar[s],  dr0, dr1);
            upk2(az[s],  dz0, dz1);
            upk2(ain[s], di0, di1);
            upk2(ahn[s], dn0, dn1);
#pragma unroll
            for (int un = 0; un < 2; un++) {
                const float dr = un ? dr1 : dr0;
                const float dz = un ? dz1 : dz0;
                const float di = un ? di1 : di0;
                const float dn = un ? dn1 : dn0;
                const float er = __expf(-dr), ez = __expf(-dz);
                const float A = 1.f + er, B = 1.f + ez;
                const float ip = rcpa(A * B);     // shared rcp for both sigmoids
                const float r  = B * ip;          // sigmoid(dr)
                const float zv = A * ip;          // sigmoid(dz)
                const float et = __expf(-2.f * (di + r * dn));
                const float n  = fmaf(2.f, rcpa(1.f + et), -1.f);   // tanh
                const float h  = n + zv * (hreg[un][s] - n);
                hreg[un][s] = h;
                sts64(H2b + s * 512 + (un ? lane + 32 : lane) * 8, splat2(h));
            }
        }
        __syncwarp();   // new h visible to all lanes
    }

    // ---- head + gumbel argmax: lane -> (sample = lane>>2 in 0..7, mode = lane&3) ----
    {
        const int sl = lane >> 2, ml = lane & 3;
        float acc = __ldg(&bhead[ml]);
#pragma unroll 8
        for (int k = 0; k < 64; k += 4) {
            const float4 wv = __ldg((const float4*)(Whead + ml * 64 + k));
            acc += wv.x * lds32f(H2b + sl * 512 + (k + 0) * 8)
                 + wv.y * lds32f(H2b + sl * 512 + (k + 1) * 8)
                 + wv.z * lds32f(H2b + sl * 512 + (k + 2) * 8)
                 + wv.w * lds32f(H2b + sl * 512 + (k + 3) * 8);
        }
        const int b = b0 + sl;
        const float lv = acc + __ldg(&gum[b * 4 + ml]);
        float best = lv;
        int   bi   = ml;
#pragma unroll
        for (int d = 1; d < 4; d <<= 1) {
            const float ob = __shfl_xor_sync(0xffffffffu, best, d);
            const int   oi = __shfl_xor_sync(0xffffffffu, bi, d);
            if (ob > best || (ob == best && oi < bi)) { best = ob; bi = oi; }
        }
        out[131072 + b * 4 + ml] = acc;                       // logits
        out[262144 + b * 4 + ml] = (ml == bi) ? 1.f : 0.f;    // onehot
        if (ml == 0) { out[393216 + b] = (float)bi; g_idx[b] = bi; }
    }
}

// Expert bank: unchanged (35us, not the bottleneck).
__global__ void __launch_bounds__(256) bank_kernel(
    const float* __restrict__ Xp,
    const float* __restrict__ dtp,
    const float* __restrict__ W1,
    const float* __restrict__ b1,
    const float* __restrict__ W2,
    const float* __restrict__ b2,
    float* __restrict__ out)
{
    __shared__ float sW1[4 * 5 * 256];
    __shared__ float sb1[4 * 256];
    __shared__ float sW2[4][256][5];
    __shared__ float sb2[16];
    const int tid = threadIdx.x;
    for (int i = tid; i < 5120; i += 256) sW1[i] = W1[i];
    for (int i = tid; i < 1024; i += 256) sb1[i] = b1[i];
    for (int i = tid; i < 4096; i += 256) sW2[i >> 10][(i >> 2) & 255][i & 3] = W2[i];
    if (tid < 16) sb2[tid] = b2[tid];
    __syncthreads();

    const float dt = __ldg(dtp);
    const int gw = blockIdx.x * 8 + (tid >> 5);
    const int lane = tid & 31;
#pragma unroll 1
    for (int it = 0; it < 8; it++) {
        const int b = gw * 8 + it;
        const int e = g_idx[b];
        const float4 xv = __ldg((const float4*)(Xp + b * 4));
        const float* w1e = sW1 + e * 1280;
        float hid[8];
#pragma unroll
        for (int j = 0; j < 8; j++) {
            const int u = lane + 32 * j;
            float a = sb1[e * 256 + u]
                    + xv.x * w1e[0 * 256 + u]
                    + xv.y * w1e[1 * 256 + u]
                    + xv.z * w1e[2 * 256 + u]
                    + xv.w * w1e[3 * 256 + u]
                    + dt   * w1e[4 * 256 + u];
            hid[j] = tanhfast(a);
        }
        float f0 = 0.f, f1 = 0.f, f2 = 0.f, f3 = 0.f;
#pragma unroll
        for (int j = 0; j < 8; j++) {
            const int u = lane + 32 * j;
            f0 += hid[j] * sW2[e][u][0];
            f1 += hid[j] * sW2[e][u][1];
            f2 += hid[j] * sW2[e][u][2];
            f3 += hid[j] * sW2[e][u][3];
        }
#pragma unroll
        for (int off = 16; off >= 1; off >>= 1) {
            f0 += __shfl_xor_sync(0xffffffffu, f0, off);
            f1 += __shfl_xor_sync(0xffffffffu, f1, off);
            f2 += __shfl_xor_sync(0xffffffffu, f2, off);
            f3 += __shfl_xor_sync(0xffffffffu, f3, off);
        }
        if (lane < 4) {
            float fv = (lane == 0) ? f0 : (lane == 1) ? f1 : (lane == 2) ? f2 : f3;
            fv += sb2[e * 4 + lane];
            out[b * 4 + lane] = __ldg(&Xp[b * 4 + lane]) + dt * fv;
        }
    }
}

extern "C" void kernel_launch(void* const* d_in, const int* in_sizes, int n_in,
                              void* d_out, int out_size) {
    const float* Hn    = (const float*)d_in[0];
    const float* Xp    = (const float*)d_in[1];
    const float* dtp   = (const float*)d_in[2];
    const float* gum   = (const float*)d_in[3];
    const float* Wih   = (const float*)d_in[4];
    const float* Whh   = (const float*)d_in[5];
    const float* bih   = (const float*)d_in[6];
    const float* bhh   = (const float*)d_in[7];
    const float* Whead = (const float*)d_in[8];
    const float* bhead = (const float*)d_in[9];
    const float* W1    = (const float*)d_in[10];
    const float* b1    = (const float*)d_in[11];
    const float* W2    = (const float*)d_in[12];
    const float* b2    = (const float*)d_in[13];
    float* out = (float*)d_out;

    const int smem = (int)sizeof(SmemGRU);   // 84 KB -> 2 CTAs/SM, 16 warps/SM
    cudaFuncSetAttribute(gru_sel_kernel, cudaFuncAttributeMaxDynamicSharedMemorySize, smem);

    gru_sel_kernel<<<512, 256, smem>>>(Hn, gum, Wih, Whh, bih, bhh, Whead, bhead, out);
    bank_kernel<<<512, 256>>>(Xp, dtp, W1, b1, W2, b2, out);
}

// round 16
// speedup vs baseline: 8.9761x; 1.2639x over previous
#include <cuda_runtime.h>
#include <cuda_bf16.h>
#include <cstdint>

#define NB 32768
#define NT 64

__device__ int g_idx[NB];

// ---------------- helpers ----------------
__device__ __forceinline__ uint32_t s2u(const void* p) {
    uint32_t a; asm("{ .reg .u64 t; cvta.to.shared.u64 t, %1; cvt.u32.u64 %0, t; }" : "=r"(a) : "l"(p)); return a;
}
__device__ __forceinline__ float rcpa(float x) {
    float r; asm("rcp.approx.ftz.f32 %0, %1;" : "=f"(r) : "f"(x)); return r;
}
__device__ __forceinline__ float tanhfast(float x) {
    float e = __expf(-2.f * x);
    return __fdividef(2.f, 1.f + e) - 1.f;
}
__device__ __forceinline__ void ldm4(uint32_t* r, uint32_t a) {
    asm volatile("ldmatrix.sync.aligned.m8n8.x4.shared.b16 {%0,%1,%2,%3}, [%4];"
        : "=r"(r[0]), "=r"(r[1]), "=r"(r[2]), "=r"(r[3]) : "r"(a));
}
__device__ __forceinline__ void ldm2(uint32_t* r, uint32_t a) {
    asm volatile("ldmatrix.sync.aligned.m8n8.x2.shared.b16 {%0,%1}, [%2];"
        : "=r"(r[0]), "=r"(r[1]) : "r"(a));
}
__device__ __forceinline__ void mma_bf16(float* d, const uint32_t* a, uint32_t b0, uint32_t b1) {
    asm volatile("mma.sync.aligned.m16n8k16.row.col.f32.bf16.bf16.f32 "
        "{%0,%1,%2,%3},{%4,%5,%6,%7},{%8,%9},{%0,%1,%2,%3};"
        : "+f"(d[0]), "+f"(d[1]), "+f"(d[2]), "+f"(d[3])
        : "r"(a[0]), "r"(a[1]), "r"(a[2]), "r"(a[3]), "r"(b0), "r"(b1));
}
__device__ __forceinline__ void sts32(uint32_t a, uint32_t v) {
    asm volatile("st.shared.b32 [%0], %1;" :: "r"(a), "r"(v) : "memory");
}
__device__ __forceinline__ uint32_t lds32(uint32_t a) {
    uint32_t v; asm volatile("ld.shared.b32 %0, [%1];" : "=r"(v) : "r"(a)); return v;
}
__device__ __forceinline__ void sts128(uint32_t a, uint32_t x, uint32_t y, uint32_t z, uint32_t w_) {
    asm volatile("st.shared.v4.b32 [%0], {%1,%2,%3,%4};" :: "r"(a), "r"(x), "r"(y), "r"(z), "r"(w_) : "memory");
}
__device__ __forceinline__ void split3(float v, unsigned short& h, unsigned short& m, unsigned short& l) {
    const __nv_bfloat16 b1 = __float2bfloat16(v);
    const float f1 = __bfloat162float(b1);
    const float r1 = v - f1;
    const __nv_bfloat16 b2 = __float2bfloat16(r1);
    const float f2 = __bfloat162float(b2);
    const __nv_bfloat16 b3 = __float2bfloat16(r1 - f2);
    h = __bfloat16_as_ushort(b1); m = __bfloat16_as_ushort(b2); l = __bfloat16_as_ushort(b3);
}
__device__ __forceinline__ float frombf(uint32_t us) {      // bf16 bits -> f32 (exact)
    return __uint_as_float(us << 16);
}
__device__ __forceinline__ uint32_t pkus(unsigned short lo, unsigned short hi) {
    return ((uint32_t)hi << 16) | (uint32_t)lo;
}
__device__ __forceinline__ float gru_act(float dr, float dz, float dnh, float dnin, float hold) {
    const float er = __expf(-dr), ez = __expf(-dz);
    const float A_ = 1.f + er, B_ = 1.f + ez;
    const float ip = rcpa(A_ * B_);
    const float r  = B_ * ip;                // sigmoid(dr)
    const float zv = A_ * ip;                // sigmoid(dz)
    const float et = __expf(-2.f * (dnin + r * dnh));
    const float n  = fmaf(2.f, rcpa(1.f + et), -1.f);
    return n + zv * (hold - n);
}

// ---------------- layout constants ----------------
#define BROW   176        // bytes per B row (88 bf16, padded for conflict-free ldmatrix)
#define BSPLIT 45056      // 256 rows * 176
#define HA_OFF 135168     // 3 * BSPLIT
#define HA_SPLIT 2816     // 16 rows * 176
#define HA_WARP  8448     // 3 splits
#define SM_TOTAL 202752   // HA_OFF + 8 warps * HA_WARP

// B row map: physical row p = 32j + 8g + i; unit u = 8j+i; g: 0=r 1=z 2=n_hh 3=n_in.
// K: 0-63 = Whh, 64-67 = Wih, 68 = bias, 69-87 = 0.
// Warp = 16 samples (m16), no inter-warp sync in the t-loop.
__global__ void __launch_bounds__(256, 1) gru_mma_kernel(
    const float* __restrict__ Hn,
    const float* __restrict__ gum,
    const float* __restrict__ Wih,
    const float* __restrict__ Whh,
    const float* __restrict__ bih,
    const float* __restrict__ bhh,
    const float* __restrict__ Whead,
    const float* __restrict__ bhead,
    float* __restrict__ out)
{
    extern __shared__ char smem[];
    const uint32_t smb = s2u(smem);
    const int tid = threadIdx.x, w = tid >> 5, l = tid & 31;

    // ---- build bf16x3-split B ----
    for (int i = tid; i < 256 * 88; i += 256) {
        const int p = i / 88, k = i % 88;
        const int j = p >> 5, g = (p >> 3) & 3, u = 8 * j + (p & 7);
        float v = 0.f;
        if (k < 64) {
            if (g == 0)      v = __ldg(&Whh[u * 64 + k]);
            else if (g == 1) v = __ldg(&Whh[(64 + u) * 64 + k]);
            else if (g == 2) v = __ldg(&Whh[(128 + u) * 64 + k]);
        } else if (k < 68) {
            const int q = k - 64;
            if (g == 0)      v = __ldg(&Wih[u * 4 + q]);
            else if (g == 1) v = __ldg(&Wih[(64 + u) * 4 + q]);
            else if (g == 3) v = __ldg(&Wih[(128 + u) * 4 + q]);
        } else if (k == 68) {
            if (g == 0)      v = __ldg(&bih[u]) + __ldg(&bhh[u]);
            else if (g == 1) v = __ldg(&bih[64 + u]) + __ldg(&bhh[64 + u]);
            else if (g == 2) v = __ldg(&bhh[128 + u]);
            else             v = __ldg(&bih[128 + u]);
        }
        unsigned short hh, mm, ll; split3(v, hh, mm, ll);
        *(unsigned short*)(smem + 0 * BSPLIT + p * BROW + 2 * k) = hh;
        *(unsigned short*)(smem + 1 * BSPLIT + p * BROW + 2 * k) = mm;
        *(unsigned short*)(smem + 2 * BSPLIT + p * BROW + 2 * k) = ll;
    }
    // ---- zero this warp's A region ----
    char* ha = smem + HA_OFF + w * HA_WARP;
    for (int i = l; i < HA_WARP / 4; i += 32) ((uint32_t*)ha)[i] = 0u;
    __syncthreads();

    const uint32_t hAb = smb + HA_OFF + w * HA_WARP;
    const int bs = blockIdx.x * 128 + w * 16 + (l & 15);   // sample for lanes 0-15 duty
    const float* xb = Hn + (size_t)bs * (NT * 4);

    // x(0) into A k-tile 4
    if (l < 16) {
        const float4 x = __ldg((const float4*)xb);
        unsigned short xh[4], xm[4], xl[4];
        const float xs[4] = {x.x, x.y, x.z, x.w};
#pragma unroll
        for (int q = 0; q < 4; q++) split3(xs[q], xh[q], xm[q], xl[q]);
        const uint32_t a0 = hAb + l * BROW + 128;
        sts128(a0 + 0 * HA_SPLIT, pkus(xh[0], xh[1]), pkus(xh[2], xh[3]), 0x3F80u, 0u);
        sts128(a0 + 1 * HA_SPLIT, pkus(xm[0], xm[1]), pkus(xm[2], xm[3]), 0u, 0u);
        sts128(a0 + 2 * HA_SPLIT, pkus(xl[0], xl[1]), pkus(xl[2], xl[3]), 0u, 0u);
    }
    __syncwarp();

    // ldmatrix lane addresses
    const uint32_t aA = hAb + (l & 15) * BROW + ((l & 16) ? 16 : 0);
    const uint32_t bR = smb + ((l & 7) + ((l & 16) ? 8 : 0)) * BROW + ((l & 8) ? 16 : 0);
    const uint32_t hOffBase = ((l >> 2)) * BROW + (2 * (l & 3)) * 2;   // + j*16 bytes, + rh*8*BROW

#pragma unroll 1
    for (int t = 0; t < NT; t++) {
        // prefetch next x
        float4 xn;
        const bool hasx = (l < 16) && (t < NT - 1);
        if (hasx) xn = __ldg((const float4*)(xb + (t + 1) * 4));

        // A fragments: 3 splits x 5 ktiles
        uint32_t Af[3][5][4];
#pragma unroll
        for (int p = 0; p < 3; p++)
#pragma unroll
            for (int kt = 0; kt < 5; kt++)
                ldm4(Af[p][kt], aA + p * HA_SPLIT + kt * 32);

#pragma unroll 1
        for (int j = 0; j < 8; j++) {
            float Dr[4] = {0, 0, 0, 0}, Dz[4] = {0, 0, 0, 0};
            float Dnh[4] = {0, 0, 0, 0}, Dnin[4] = {0, 0, 0, 0};
            const uint32_t bG = bR + j * (32 * BROW);
#pragma unroll
            for (int pb = 0; pb < 3; pb++) {
                const uint32_t bb = bG + pb * BSPLIT;
                uint32_t rz[5][4], nh4[4][2], nx[4];
#pragma unroll
                for (int kt = 0; kt < 5; kt++) ldm4(rz[kt], bb + kt * 32);
#pragma unroll
                for (int kt = 0; kt < 4; kt++) ldm2(nh4[kt], bb + 16 * BROW + kt * 32);
                ldm4(nx, bb + 16 * BROW + 128);
                const int npa = (pb == 0) ? 3 : ((pb == 1) ? 2 : 1);
#pragma unroll
                for (int pa = 0; pa < 3; pa++) {
                    if (pa < npa) {
#pragma unroll
                        for (int kt = 0; kt < 5; kt++) {
                            mma_bf16(Dr, Af[pa][kt], rz[kt][0], rz[kt][1]);
                            mma_bf16(Dz, Af[pa][kt], rz[kt][2], rz[kt][3]);
                            if (kt < 4) mma_bf16(Dnh, Af[pa][kt], nh4[kt][0], nh4[kt][1]);
                            else        mma_bf16(Dnh, Af[pa][kt], nx[0], nx[1]);
                        }
                        mma_bf16(Dnin, Af[pa][4], nx[2], nx[3]);
                    }
                }
            }
            // activations + h writeback (units 8j+2(l&3)+{0,1}; rows l>>2, l>>2+8)
#pragma unroll
            for (int rh = 0; rh < 2; rh++) {
                const uint32_t off = hOffBase + rh * (8 * BROW) + j * 16;
                const uint32_t ph = lds32(hAb + 0 * HA_SPLIT + off);
                const uint32_t pm = lds32(hAb + 1 * HA_SPLIT + off);
                const uint32_t pl_ = lds32(hAb + 2 * HA_SPLIT + off);
                const float hold0 = frombf(ph & 0xFFFFu) + frombf(pm & 0xFFFFu) + frombf(pl_ & 0xFFFFu);
                const float hold1 = frombf(ph >> 16) + frombf(pm >> 16) + frombf(pl_ >> 16);
                const int q0 = 2 * rh, q1 = q0 + 1;
                const float h0 = gru_act(Dr[q0], Dz[q0], Dnh[q0], Dnin[q0], hold0);
                const float h1 = gru_act(Dr[q1], Dz[q1], Dnh[q1], Dnin[q1], hold1);
                unsigned short ah, am, al, bh2, bm2, bl2;
                split3(h0, ah, am, al);
                split3(h1, bh2, bm2, bl2);
                sts32(hAb + 0 * HA_SPLIT + off, pkus(ah, bh2));
                sts32(hAb + 1 * HA_SPLIT + off, pkus(am, bm2));
                sts32(hAb + 2 * HA_SPLIT + off, pkus(al, bl2));
            }
        }
        // store x(t+1)
        if (hasx) {
            unsigned short xh[4], xm[4], xl[4];
            const float xs[4] = {xn.x, xn.y, xn.z, xn.w};
#pragma unroll
            for (int q = 0; q < 4; q++) split3(xs[q], xh[q], xm[q], xl[q]);
            const uint32_t a0 = hAb + l * BROW + 128;
            sts128(a0 + 0 * HA_SPLIT, pkus(xh[0], xh[1]), pkus(xh[2], xh[3]), 0x3F80u, 0u);
            sts128(a0 + 1 * HA_SPLIT, pkus(xm[0], xm[1]), pkus(xm[2], xm[3]), 0u, 0u);
            sts128(a0 + 2 * HA_SPLIT, pkus(xl[0], xl[1]), pkus(xl[2], xl[3]), 0u, 0u);
        }
        __syncwarp();
    }

    // ---- head: reconstruct final h from A splits, accumulate logits ----
    float lg0[4] = {0, 0, 0, 0}, lg8[4] = {0, 0, 0, 0};
#pragma unroll
    for (int j = 0; j < 8; j++) {
        float2 wv[4];
#pragma unroll
        for (int m = 0; m < 4; m++)
            wv[m] = __ldg((const float2*)(Whead + m * 64 + 8 * j + 2 * (l & 3)));
#pragma unroll
        for (int rh = 0; rh < 2; rh++) {
            const uint32_t off = hOffBase + rh * (8 * BROW) + j * 16;
            const uint32_t ph = lds32(hAb + 0 * HA_SPLIT + off);
            const uint32_t pm = lds32(hAb + 1 * HA_SPLIT + off);
            const uint32_t pl_ = lds32(hAb + 2 * HA_SPLIT + off);
            const float h0 = frombf(ph & 0xFFFFu) + frombf(pm & 0xFFFFu) + frombf(pl_ & 0xFFFFu);
            const float h1 = frombf(ph >> 16) + frombf(pm >> 16) + frombf(pl_ >> 16);
#pragma unroll
            for (int m = 0; m < 4; m++) {
                const float c = wv[m].x * h0 + wv[m].y * h1;
                if (rh) lg8[m] += c; else lg0[m] += c;
            }
        }
    }
#pragma unroll
    for (int m = 0; m < 4; m++) {
        lg0[m] += __shfl_xor_sync(0xffffffffu, lg0[m], 1);
        lg0[m] += __shfl_xor_sync(0xffffffffu, lg0[m], 2);
        lg8[m] += __shfl_xor_sync(0xffffffffu, lg8[m], 1);
        lg8[m] += __shfl_xor_sync(0xffffffffu, lg8[m], 2);
    }
    if ((l & 3) == 0) {
        const int s = l >> 2;
#pragma unroll
        for (int rh = 0; rh < 2; rh++) {
            const int b = blockIdx.x * 128 + w * 16 + s + rh * 8;
            float lg[4];
#pragma unroll
            for (int m = 0; m < 4; m++) lg[m] = (rh ? lg8[m] : lg0[m]) + __ldg(&bhead[m]);
            const float4 gv = __ldg((const float4*)(gum + b * 4));
            const float v0 = lg[0] + gv.x, v1 = lg[1] + gv.y, v2 = lg[2] + gv.z, v3 = lg[3] + gv.w;
            int bi = 0; float best = v0;
            if (v1 > best) { best = v1; bi = 1; }
            if (v2 > best) { best = v2; bi = 2; }
            if (v3 > best) { best = v3; bi = 3; }
#pragma unroll
            for (int m = 0; m < 4; m++) {
                out[131072 + b * 4 + m] = lg[m];
                out[262144 + b * 4 + m] = (m == bi) ? 1.f : 0.f;
            }
            out[393216 + b] = (float)bi;
            g_idx[b] = bi;
        }
    }
}

// ---------------- Expert bank (unchanged, 35us) ----------------
__global__ void __launch_bounds__(256) bank_kernel(
    const float* __restrict__ Xp,
    const float* __restrict__ dtp,
    const float* __restrict__ W1,
    const float* __restrict__ b1,
    const float* __restrict__ W2,
    const float* __restrict__ b2,
    float* __restrict__ out)
{
    __shared__ float sW1[4 * 5 * 256];
    __shared__ float sb1[4 * 256];
    __shared__ float sW2[4][256][5];
    __shared__ float sb2[16];
    const int tid = threadIdx.x;
    for (int i = tid; i < 5120; i += 256) sW1[i] = W1[i];
    for (int i = tid; i < 1024; i += 256) sb1[i] = b1[i];
    for (int i = tid; i < 4096; i += 256) sW2[i >> 10][(i >> 2) & 255][i & 3] = W2[i];
    if (tid < 16) sb2[tid] = b2[tid];
    __syncthreads();

    const float dt = __ldg(dtp);
    const int gw = blockIdx.x * 8 + (tid >> 5);
    const int lane = tid & 31;
#pragma unroll 1
    for (int it = 0; it < 8; it++) {
        const int b = gw * 8 + it;
        const int e = g_idx[b];
        const float4 xv = __ldg((const float4*)(Xp + b * 4));
        const float* w1e = sW1 + e * 1280;
        float hid[8];
#pragma unroll
        for (int j = 0; j < 8; j++) {
            const int u = lane + 32 * j;
            float a = sb1[e * 256 + u]
                    + xv.x * w1e[0 * 256 + u]
                    + xv.y * w1e[1 * 256 + u]
                    + xv.z * w1e[2 * 256 + u]
                    + xv.w * w1e[3 * 256 + u]
                    + dt   * w1e[4 * 256 + u];
            hid[j] = tanhfast(a);
        }
        float f0 = 0.f, f1 = 0.f, f2 = 0.f, f3 = 0.f;
#pragma unroll
        for (int j = 0; j < 8; j++) {
            const int u = lane + 32 * j;
            f0 += hid[j] * sW2[e][u][0];
            f1 += hid[j] * sW2[e][u][1];
            f2 += hid[j] * sW2[e][u][2];
            f3 += hid[j] * sW2[e][u][3];
        }
#pragma unroll
        for (int off = 16; off >= 1; off >>= 1) {
            f0 += __shfl_xor_sync(0xffffffffu, f0, off);
            f1 += __shfl_xor_sync(0xffffffffu, f1, off);
            f2 += __shfl_xor_sync(0xffffffffu, f2, off);
            f3 += __shfl_xor_sync(0xffffffffu, f3, off);
        }
        if (lane < 4) {
            float fv = (lane == 0) ? f0 : (lane == 1) ? f1 : (lane == 2) ? f2 : f3;
            fv += sb2[e * 4 + lane];
            out[b * 4 + lane] = __ldg(&Xp[b * 4 + lane]) + dt * fv;
        }
    }
}

extern "C" void kernel_launch(void* const* d_in, const int* in_sizes, int n_in,
                              void* d_out, int out_size) {
    const float* Hn    = (const float*)d_in[0];
    const float* Xp    = (const float*)d_in[1];
    const float* dtp   = (const float*)d_in[2];
    const float* gum   = (const float*)d_in[3];
    const float* Wih   = (const float*)d_in[4];
    const float* Whh   = (const float*)d_in[5];
    const float* bih   = (const float*)d_in[6];
    const float* bhh   = (const float*)d_in[7];
    const float* Whead = (const float*)d_in[8];
    const float* bhead = (const float*)d_in[9];
    const float* W1    = (const float*)d_in[10];
    const float* b1    = (const float*)d_in[11];
    const float* W2    = (const float*)d_in[12];
    const float* b2    = (const float*)d_in[13];
    float* out = (float*)d_out;

    cudaFuncSetAttribute(gru_mma_kernel, cudaFuncAttributeMaxDynamicSharedMemorySize, SM_TOTAL);
    gru_mma_kernel<<<256, 256, SM_TOTAL>>>(Hn, gum, Wih, Whh, bih, bhh, Whead, bhead, out);
    bank_kernel<<<512, 256>>>(Xp, dtp, W1, b1, W2, b2, out);
}

// round 17
// speedup vs baseline: 14.4548x; 1.6104x over previous
#include <cuda_runtime.h>
#include <cuda_fp16.h>
#include <cstdint>

#define NB 32768
#define NT 64

__device__ int g_idx[NB];

// ---------------- helpers ----------------
__device__ __forceinline__ uint32_t s2u(const void* p) {
    uint32_t a; asm("{ .reg .u64 t; cvta.to.shared.u64 t, %1; cvt.u32.u64 %0, t; }" : "=r"(a) : "l"(p)); return a;
}
__device__ __forceinline__ float rcpa(float x) {
    float r; asm("rcp.approx.ftz.f32 %0, %1;" : "=f"(r) : "f"(x)); return r;
}
__device__ __forceinline__ float tanhfast(float x) {
    float e = __expf(-2.f * x);
    return __fdividef(2.f, 1.f + e) - 1.f;
}
__device__ __forceinline__ void ldm4(uint32_t* r, uint32_t a) {
    asm volatile("ldmatrix.sync.aligned.m8n8.x4.shared.b16 {%0,%1,%2,%3}, [%4];"
        : "=r"(r[0]), "=r"(r[1]), "=r"(r[2]), "=r"(r[3]) : "r"(a));
}
__device__ __forceinline__ void ldm2(uint32_t* r, uint32_t a) {
    asm volatile("ldmatrix.sync.aligned.m8n8.x2.shared.b16 {%0,%1}, [%2];"
        : "=r"(r[0]), "=r"(r[1]) : "r"(a));
}
__device__ __forceinline__ void mma_f16(float* d, const uint32_t* a, uint32_t b0, uint32_t b1) {
    asm volatile("mma.sync.aligned.m16n8k16.row.col.f32.f16.f16.f32 "
        "{%0,%1,%2,%3},{%4,%5,%6,%7},{%8,%9},{%0,%1,%2,%3};"
        : "+f"(d[0]), "+f"(d[1]), "+f"(d[2]), "+f"(d[3])
        : "r"(a[0]), "r"(a[1]), "r"(a[2]), "r"(a[3]), "r"(b0), "r"(b1));
}
__device__ __forceinline__ void sts32(uint32_t a, uint32_t v) {
    asm volatile("st.shared.b32 [%0], %1;" :: "r"(a), "r"(v) : "memory");
}
__device__ __forceinline__ uint32_t lds32(uint32_t a) {
    uint32_t v; asm volatile("ld.shared.b32 %0, [%1];" : "=r"(v) : "r"(a)); return v;
}
__device__ __forceinline__ void sts128(uint32_t a, uint32_t x, uint32_t y, uint32_t z, uint32_t w_) {
    asm volatile("st.shared.v4.b32 [%0], {%1,%2,%3,%4};" :: "r"(a), "r"(x), "r"(y), "r"(z), "r"(w_) : "memory");
}
__device__ __forceinline__ unsigned short f2h(float v) { return __half_as_ushort(__float2half_rn(v)); }
__device__ __forceinline__ float h2f(unsigned short u) { return __half2float(__ushort_as_half(u)); }
// fp16 scaled 2-split: v ~= vh + vm/2048, residual ~2^-22|v|
__device__ __forceinline__ void split2(float v, unsigned short& h, unsigned short& m) {
    h = f2h(v);
    m = f2h((v - h2f(h)) * 2048.f);
}
__device__ __forceinline__ uint32_t pkus(unsigned short lo, unsigned short hi) {
    return ((uint32_t)hi << 16) | (uint32_t)lo;
}
#define ISC 4.8828125e-4f   // 1/2048
__device__ __forceinline__ float gru_act(float dr, float dz, float dnh, float dnin, float hold) {
    const float er = __expf(-dr), ez = __expf(-dz);
    const float A_ = 1.f + er, B_ = 1.f + ez;
    const float ip = rcpa(A_ * B_);
    const float r  = B_ * ip;
    const float zv = A_ * ip;
    const float et = __expf(-2.f * (dnin + r * dnh));
    const float n  = fmaf(2.f, rcpa(1.f + et), -1.f);
    return n + zv * (hold - n);
}

// ---------------- layout constants (B map & strides proven in R16) ----------------
#define BROW   176        // bytes per row (88 fp16, conflict-free ldmatrix)
#define BSPLIT 45056      // 256 rows * 176
#define HA_OFF 90112      // 2 * BSPLIT
#define HA_SPLIT 2816     // 16 rows * 176
#define HA_WARP  5632     // 2 splits
#define SM_TOTAL 135168   // HA_OFF + 8 warps * HA_WARP

// B row map: p = 32j + 8g + i; unit u = 8j+i; g: 0=r 1=z 2=n_hh 3=n_in.
// K: 0-63 Whh, 64-67 Wih, 68 bias, 69-87 zero.  3-term schedule:
//   T1 += Ahi x Bhi ; T2 += Amid x Bhi + Ahi x Bmid ; D = T1 + T2/2048.
__global__ void __launch_bounds__(256, 1) gru_mma_kernel(
    const float* __restrict__ Hn,
    const float* __restrict__ gum,
    const float* __restrict__ Wih,
    const float* __restrict__ Whh,
    const float* __restrict__ bih,
    const float* __restrict__ bhh,
    const float* __restrict__ Whead,
    const float* __restrict__ bhead,
    float* __restrict__ out)
{
    extern __shared__ char smem[];
    const uint32_t smb = s2u(smem);
    const int tid = threadIdx.x, w = tid >> 5, l = tid & 31;

    // ---- build fp16x2-split B ----
    for (int i = tid; i < 256 * 88; i += 256) {
        const int p = i / 88, k = i % 88;
        const int j = p >> 5, g = (p >> 3) & 3, u = 8 * j + (p & 7);
        float v = 0.f;
        if (k < 64) {
            if (g == 0)      v = __ldg(&Whh[u * 64 + k]);
            else if (g == 1) v = __ldg(&Whh[(64 + u) * 64 + k]);
            else if (g == 2) v = __ldg(&Whh[(128 + u) * 64 + k]);
        } else if (k < 68) {
            const int q = k - 64;
            if (g == 0)      v = __ldg(&Wih[u * 4 + q]);
            else if (g == 1) v = __ldg(&Wih[(64 + u) * 4 + q]);
            else if (g == 3) v = __ldg(&Wih[(128 + u) * 4 + q]);
        } else if (k == 68) {
            if (g == 0)      v = __ldg(&bih[u]) + __ldg(&bhh[u]);
            else if (g == 1) v = __ldg(&bih[64 + u]) + __ldg(&bhh[64 + u]);
            else if (g == 2) v = __ldg(&bhh[128 + u]);
            else             v = __ldg(&bih[128 + u]);
        }
        unsigned short hh, mm; split2(v, hh, mm);
        *(unsigned short*)(smem + 0 * BSPLIT + p * BROW + 2 * k) = hh;
        *(unsigned short*)(smem + 1 * BSPLIT + p * BROW + 2 * k) = mm;
    }
    // ---- zero this warp's A region ----
    char* ha = smem + HA_OFF + w * HA_WARP;
    for (int i = l; i < HA_WARP / 4; i += 32) ((uint32_t*)ha)[i] = 0u;
    __syncthreads();

    const uint32_t hAb = smb + HA_OFF + w * HA_WARP;
    const int bs = blockIdx.x * 128 + w * 16 + (l & 15);
    const float* xb = Hn + (size_t)bs * (NT * 4);

    // x(0) + const-1 into A k-tile 4 (hi split gets 1.0 at k=68; mid gets 0)
    if (l < 16) {
        const float4 x = __ldg((const float4*)xb);
        unsigned short xh[4], xm[4];
        const float xs[4] = {x.x, x.y, x.z, x.w};
#pragma unroll
        for (int q = 0; q < 4; q++) split2(xs[q], xh[q], xm[q]);
        const uint32_t a0 = hAb + l * BROW + 128;
        sts128(a0 + 0 * HA_SPLIT, pkus(xh[0], xh[1]), pkus(xh[2], xh[3]), 0x3C00u, 0u);
        sts128(a0 + 1 * HA_SPLIT, pkus(xm[0], xm[1]), pkus(xm[2], xm[3]), 0u, 0u);
    }
    __syncwarp();

    // ldmatrix lane addresses (identical to proven R16)
    const uint32_t aA = hAb + (l & 15) * BROW + ((l & 16) ? 16 : 0);
    const uint32_t bR = smb + ((l & 7) + ((l & 16) ? 8 : 0)) * BROW + ((l & 8) ? 16 : 0);
    const uint32_t hOffBase = ((l >> 2)) * BROW + (2 * (l & 3)) * 2;

#pragma unroll 1
    for (int t = 0; t < NT; t++) {
        float4 xn;
        const bool hasx = (l < 16) && (t < NT - 1);
        if (hasx) xn = __ldg((const float4*)(xb + (t + 1) * 4));

        // A fragments: 2 splits x 5 ktiles
        uint32_t Af[2][5][4];
#pragma unroll
        for (int p = 0; p < 2; p++)
#pragma unroll
            for (int kt = 0; kt < 5; kt++)
                ldm4(Af[p][kt], aA + p * HA_SPLIT + kt * 32);

#pragma unroll 1
        for (int j = 0; j < 8; j++) {
            float T1r[4] = {0,0,0,0}, T1z[4] = {0,0,0,0}, T1h[4] = {0,0,0,0}, T1i[4] = {0,0,0,0};
            float T2r[4] = {0,0,0,0}, T2z[4] = {0,0,0,0}, T2h[4] = {0,0,0,0}, T2i[4] = {0,0,0,0};
            const uint32_t bG = bR + j * (32 * BROW);

#define ACCUM(AF, DR, DZ, DH, DI)                                          \
            {   _Pragma("unroll")                                          \
                for (int kt = 0; kt < 5; kt++) {                           \
                    mma_f16(DR, AF[kt], rz[kt][0], rz[kt][1]);             \
                    mma_f16(DZ, AF[kt], rz[kt][2], rz[kt][3]);             \
                    if (kt < 4) mma_f16(DH, AF[kt], nh4[kt][0], nh4[kt][1]); \
                    else        mma_f16(DH, AF[kt], nx[0], nx[1]);         \
                }                                                          \
                mma_f16(DI, AF[4], nx[2], nx[3]); }

            {   // B hi split: T1 += Ahi*Bhi ; T2 += Amid*Bhi
                const uint32_t bb = bG + 0 * BSPLIT;
                uint32_t rz[5][4], nh4[4][2], nx[4];
#pragma unroll
                for (int kt = 0; kt < 5; kt++) ldm4(rz[kt], bb + kt * 32);
#pragma unroll
                for (int kt = 0; kt < 4; kt++) ldm2(nh4[kt], bb + 16 * BROW + kt * 32);
                ldm4(nx, bb + 16 * BROW + 128);
                ACCUM(Af[0], T1r, T1z, T1h, T1i)
                ACCUM(Af[1], T2r, T2z, T2h, T2i)
            }
            {   // B mid split: T2 += Ahi*Bmid
                const uint32_t bb = bG + 1 * BSPLIT;
                uint32_t rz[5][4], nh4[4][2], nx[4];
#pragma unroll
                for (int kt = 0; kt < 5; kt++) ldm4(rz[kt], bb + kt * 32);
#pragma unroll
                for (int kt = 0; kt < 4; kt++) ldm2(nh4[kt], bb + 16 * BROW + kt * 32);
                ldm4(nx, bb + 16 * BROW + 128);
                ACCUM(Af[0], T2r, T2z, T2h, T2i)
            }
#undef ACCUM

            // activations + h writeback
#pragma unroll
            for (int rh = 0; rh < 2; rh++) {
                const uint32_t off = hOffBase + rh * (8 * BROW) + j * 16;
                const uint32_t ph = lds32(hAb + 0 * HA_SPLIT + off);
                const uint32_t pm = lds32(hAb + 1 * HA_SPLIT + off);
                const float hold0 = h2f(ph & 0xFFFFu) + h2f(pm & 0xFFFFu) * ISC;
                const float hold1 = h2f(ph >> 16) + h2f(pm >> 16) * ISC;
                const int q0 = 2 * rh, q1 = q0 + 1;
                const float dr0 = T1r[q0] + T2r[q0] * ISC, dr1 = T1r[q1] + T2r[q1] * ISC;
                const float dz0 = T1z[q0] + T2z[q0] * ISC, dz1 = T1z[q1] + T2z[q1] * ISC;
                const float dh0 = T1h[q0] + T2h[q0] * ISC, dh1 = T1h[q1] + T2h[q1] * ISC;
                const float di0 = T1i[q0] + T2i[q0] * ISC, di1 = T1i[q1] + T2i[q1] * ISC;
                const float h0 = gru_act(dr0, dz0, dh0, di0, hold0);
                const float h1 = gru_act(dr1, dz1, dh1, di1, hold1);
                unsigned short ah, am, bh2, bm2;
                split2(h0, ah, am);
                split2(h1, bh2, bm2);
                sts32(hAb + 0 * HA_SPLIT + off, pkus(ah, bh2));
                sts32(hAb + 1 * HA_SPLIT + off, pkus(am, bm2));
            }
        }
        // store x(t+1)
        if (hasx) {
            unsigned short xh[4], xm[4];
            const float xs[4] = {xn.x, xn.y, xn.z, xn.w};
#pragma unroll
            for (int q = 0; q < 4; q++) split2(xs[q], xh[q], xm[q]);
            const uint32_t a0 = hAb + l * BROW + 128;
            sts128(a0 + 0 * HA_SPLIT, pkus(xh[0], xh[1]), pkus(xh[2], xh[3]), 0x3C00u, 0u);
            sts128(a0 + 1 * HA_SPLIT, pkus(xm[0], xm[1]), pkus(xm[2], xm[3]), 0u, 0u);
        }
        __syncwarp();
    }

    // ---- head: reconstruct final h, accumulate logits ----
    float lg0[4] = {0, 0, 0, 0}, lg8[4] = {0, 0, 0, 0};
#pragma unroll
    for (int j = 0; j < 8; j++) {
        float2 wv[4];
#pragma unroll
        for (int m = 0; m < 4; m++)
            wv[m] = __ldg((const float2*)(Whead + m * 64 + 8 * j + 2 * (l & 3)));
#pragma unroll
        for (int rh = 0; rh < 2; rh++) {
            const uint32_t off = hOffBase + rh * (8 * BROW) + j * 16;
            const uint32_t ph = lds32(hAb + 0 * HA_SPLIT + off);
            const uint32_t pm = lds32(hAb + 1 * HA_SPLIT + off);
            const float h0 = h2f(ph & 0xFFFFu) + h2f(pm & 0xFFFFu) * ISC;
            const float h1 = h2f(ph >> 16) + h2f(pm >> 16) * ISC;
#pragma unroll
            for (int m = 0; m < 4; m++) {
                const float c = wv[m].x * h0 + wv[m].y * h1;
                if (rh) lg8[m] += c; else lg0[m] += c;
            }
        }
    }
#pragma unroll
    for (int m = 0; m < 4; m++) {
        lg0[m] += __shfl_xor_sync(0xffffffffu, lg0[m], 1);
        lg0[m] += __shfl_xor_sync(0xffffffffu, lg0[m], 2);
        lg8[m] += __shfl_xor_sync(0xffffffffu, lg8[m], 1);
        lg8[m] += __shfl_xor_sync(0xffffffffu, lg8[m], 2);
    }
    if ((l & 3) == 0) {
        const int s = l >> 2;
#pragma unroll
        for (int rh = 0; rh < 2; rh++) {
            const int b = blockIdx.x * 128 + w * 16 + s + rh * 8;
            float lg[4];
#pragma unroll
            for (int m = 0; m < 4; m++) lg[m] = (rh ? lg8[m] : lg0[m]) + __ldg(&bhead[m]);
            const float4 gv = __ldg((const float4*)(gum + b * 4));
            const float v0 = lg[0] + gv.x, v1 = lg[1] + gv.y, v2 = lg[2] + gv.z, v3 = lg[3] + gv.w;
            int bi = 0; float best = v0;
            if (v1 > best) { best = v1; bi = 1; }
            if (v2 > best) { best = v2; bi = 2; }
            if (v3 > best) { best = v3; bi = 3; }
#pragma unroll
            for (int m = 0; m < 4; m++) {
                out[131072 + b * 4 + m] = lg[m];
                out[262144 + b * 4 + m] = (m == bi) ? 1.f : 0.f;
            }
            out[393216 + b] = (float)bi;
            g_idx[b] = bi;
        }
    }
}

// ---------------- Expert bank (unchanged, 35us) ----------------
__global__ void __launch_bounds__(256) bank_kernel(
    const float* __restrict__ Xp,
    const float* __restrict__ dtp,
    const float* __restrict__ W1,
    const float* __restrict__ b1,
    const float* __restrict__ W2,
    const float* __restrict__ b2,
    float* __restrict__ out)
{
    __shared__ float sW1[4 * 5 * 256];
    __shared__ float sb1[4 * 256];
    __shared__ float sW2[4][256][5];
    __shared__ float sb2[16];
    const int tid = threadIdx.x;
    for (int i = tid; i < 5120; i += 256) sW1[i] = W1[i];
    for (int i = tid; i < 1024; i += 256) sb1[i] = b1[i];
    for (int i = tid; i < 4096; i += 256) sW2[i >> 10][(i >> 2) & 255][i & 3] = W2[i];
    if (tid < 16) sb2[tid] = b2[tid];
    __syncthreads();

    const float dt = __ldg(dtp);
    const int gw = blockIdx.x * 8 + (tid >> 5);
    const int lane = tid & 31;
#pragma unroll 1
    for (int it = 0; it < 8; it++) {
        const int b = gw * 8 + it;
        const int e = g_idx[b];
        const float4 xv = __ldg((const float4*)(Xp + b * 4));
        const float* w1e = sW1 + e * 1280;
        float hid[8];
#pragma unroll
        for (int j = 0; j < 8; j++) {
            const int u = lane + 32 * j;
            float a = sb1[e * 256 + u]
                    + xv.x * w1e[0 * 256 + u]
                    + xv.y * w1e[1 * 256 + u]
                    + xv.z * w1e[2 * 256 + u]
                    + xv.w * w1e[3 * 256 + u]
                    + dt   * w1e[4 * 256 + u];
            hid[j] = tanhfast(a);
        }
        float f0 = 0.f, f1 = 0.f, f2 = 0.f, f3 = 0.f;
#pragma unroll
        for (int j = 0; j < 8; j++) {
            const int u = lane + 32 * j;
            f0 += hid[j] * sW2[e][u][0];
            f1 += hid[j] * sW2[e][u][1];
            f2 += hid[j] * sW2[e][u][2];
            f3 += hid[j] * sW2[e][u][3];
        }
#pragma unroll
        for (int off = 16; off >= 1; off >>= 1) {
            f0 += __shfl_xor_sync(0xffffffffu, f0, off);
            f1 += __shfl_xor_sync(0xffffffffu, f1, off);
            f2 += __shfl_xor_sync(0xffffffffu, f2, off);
            f3 += __shfl_xor_sync(0xffffffffu, f3, off);
        }
        if (lane < 4) {
            float fv = (lane == 0) ? f0 : (lane == 1) ? f1 : (lane == 2) ? f2 : f3;
            fv += sb2[e * 4 + lane];
            out[b * 4 + lane] = __ldg(&Xp[b * 4 + lane]) + dt * fv;
        }
    }
}

extern "C" void kernel_launch(void* const* d_in, const int* in_sizes, int n_in,
                              void* d_out, int out_size) {
    const float* Hn    = (const float*)d_in[0];
    const float* Xp    = (const float*)d_in[1];
    const float* dtp   = (const float*)d_in[2];
    const float* gum   = (const float*)d_in[3];
    const float* Wih   = (const float*)d_in[4];
    const float* Whh   = (const float*)d_in[5];
    const float* bih   = (const float*)d_in[6];
    const float* bhh   = (const float*)d_in[7];
    const float* Whead = (const float*)d_in[8];
    const float* bhead = (const float*)d_in[9];
    const float* W1    = (const float*)d_in[10];
    const float* b1    = (const float*)d_in[11];
    const float* W2    = (const float*)d_in[12];
    const float* b2    = (const float*)d_in[13];
    float* out = (float*)d_out;

    cudaFuncSetAttribute(gru_mma_kernel, cudaFuncAttributeMaxDynamicSharedMemorySize, SM_TOTAL);
    gru_mma_kernel<<<256, 256, SM_TOTAL>>>(Hn, gum, Wih, Whh, bih, bhh, Whead, bhead, out);
    bank_kernel<<<512, 256>>>(Xp, dtp, W1, b1, W2, b2, out);
}